// round 6
// baseline (speedup 1.0000x reference)
#include <cuda_runtime.h>
#include <math.h>

#define N_NODES   50000
#define N_HE      20000
#define N_PAIRS   400000
#define E_EDGES   800000
#define E2        (E_EDGES + N_NODES)
#define L_EDGES   100000

// ---------------- scratch (device globals; no runtime allocation) ----------------
__device__ float g_h0[N_NODES * 256];   // reused: m128 (20000x128) pre-GEMM hyperedge sums
__device__ float g_m [N_HE    * 256];   // hyperedge messages post-GEMM
__device__ float g_h1[N_NODES * 256];   // activations (reused across layers)
__device__ float g_hg[N_NODES * 256];   // GEMM output features
__device__ float g_as[N_NODES];
__device__ float g_ad[N_NODES];
__device__ float g_z [N_NODES * 64];

__device__ int c_cnt_he[N_HE],    c_off_he[N_HE],    c_cur_he[N_HE],    c_val_he[N_PAIRS];
__device__ int c_cnt_nd[N_NODES], c_off_nd[N_NODES], c_cur_nd[N_NODES], c_val_nd[N_PAIRS];
__device__ int c_cnt_g [N_NODES], c_off_g [N_NODES], c_cur_g [N_NODES], c_val_g [E2];

typedef unsigned long long u64;

__device__ __forceinline__ float lrelu02(float x) { return x > 0.f ? x : 0.2f * x; }
__device__ __forceinline__ void f4add(float4& a, const float4 b) {
    a.x += b.x; a.y += b.y; a.z += b.z; a.w += b.w;
}
__device__ __forceinline__ void f4fma(float4& a, float w, const float4 b) {
    a.x = fmaf(w, b.x, a.x); a.y = fmaf(w, b.y, a.y);
    a.z = fmaf(w, b.z, a.z); a.w = fmaf(w, b.w, a.w);
}
// ---- packed fp32x2 (Blackwell FFMA2) ----
__device__ __forceinline__ u64 pk2(float lo, float hi) {
    u64 r; asm("mov.b64 %0, {%1, %2};" : "=l"(r) : "f"(lo), "f"(hi)); return r;
}
__device__ __forceinline__ u64 dup2(float x) { return pk2(x, x); }
__device__ __forceinline__ void unpk2(float& lo, float& hi, u64 v) {
    asm("mov.b64 {%0, %1}, %2;" : "=f"(lo), "=f"(hi) : "l"(v));
}
__device__ __forceinline__ void fma2(u64& d, u64 a, u64 b) {
    asm("fma.rn.f32x2 %0, %1, %2, %0;" : "+l"(d) : "l"(a), "l"(b));
}
__device__ __forceinline__ void add2(u64& d, u64 a) {
    asm("add.rn.f32x2 %0, %0, %1;" : "+l"(d) : "l"(a));
}

// ---------------- GEMM: C[M,N] = A[M,K] @ B[K,N], fp32, f32x2 core, double-buffered.
// FUSE: also computes per-row dots C_row . av_s -> atomicAdd g_as, same for av_d.
template<int BM, int BN, int BK, int TM, int TN, bool FUSE>
__global__ void __launch_bounds__((BM / TM) * (BN / TN))
sgemm(const float* __restrict__ A, const float* __restrict__ B, float* __restrict__ C,
      int M, int N, int K,
      const float* __restrict__ av_s, const float* __restrict__ av_d,
      float* __restrict__ dot_s, float* __restrict__ dot_d) {
    constexpr int NT = (BM / TM) * (BN / TN);
    constexpr int LA = BM * BK / 4 / NT;
    constexpr int LB = BK * BN / 4 / NT;
    __shared__ float As[2][BK][BM + 4];
    __shared__ float Bs[2][BK][BN];
    const int tid = threadIdx.x;
    const int tx = tid % (BN / TN);
    const int ty = tid / (BN / TN);
    const int rowBase = blockIdx.y * BM, colBase = blockIdx.x * BN;
    float4 ra[LA], rb[LB];

    auto loadA = [&](int k0) {
        #pragma unroll
        for (int s = 0; s < LA; s++) {
            int f = tid + s * NT;
            int r = f / (BK / 4), c = (f % (BK / 4)) * 4;
            int gr = rowBase + r;
            ra[s] = (gr < M) ? *(const float4*)&A[(size_t)gr * K + k0 + c]
                             : make_float4(0.f, 0.f, 0.f, 0.f);
        }
    };
    auto loadB = [&](int k0) {
        #pragma unroll
        for (int s = 0; s < LB; s++) {
            int f = tid + s * NT;
            int r = f / (BN / 4), c = (f % (BN / 4)) * 4;
            rb[s] = *(const float4*)&B[(size_t)(k0 + r) * N + colBase + c];
        }
    };
    auto stA = [&](int buf) {
        #pragma unroll
        for (int s = 0; s < LA; s++) {
            int f = tid + s * NT;
            int r = f / (BK / 4), c = (f % (BK / 4)) * 4;
            As[buf][c + 0][r] = ra[s].x; As[buf][c + 1][r] = ra[s].y;
            As[buf][c + 2][r] = ra[s].z; As[buf][c + 3][r] = ra[s].w;
        }
    };
    auto stB = [&](int buf) {
        #pragma unroll
        for (int s = 0; s < LB; s++) {
            int f = tid + s * NT;
            int r = f / (BN / 4), c = (f % (BN / 4)) * 4;
            *(float4*)&Bs[buf][r][c] = rb[s];
        }
    };

    u64 acc[TM][TN / 2];
    #pragma unroll
    for (int i = 0; i < TM; i++)
        #pragma unroll
        for (int j = 0; j < TN / 2; j++) acc[i][j] = 0ULL;

    loadA(0); loadB(0); stA(0); stB(0);
    __syncthreads();
    const int T = K / BK;
    int cur = 0;
    for (int t = 0; t < T; t++) {
        if (t + 1 < T) { loadA((t + 1) * BK); loadB((t + 1) * BK); }
        #pragma unroll
        for (int k = 0; k < BK; k++) {
            float af[TM], bf[TN];
            #pragma unroll
            for (int i = 0; i < TM; i += 4)
                *(float4*)&af[i] = *(const float4*)&As[cur][k][ty * TM + i];
            #pragma unroll
            for (int j = 0; j < TN; j += 4)
                *(float4*)&bf[j] = *(const float4*)&Bs[cur][k][tx * TN + j];
            u64 a2[TM], b2[TN / 2];
            #pragma unroll
            for (int i = 0; i < TM; i++) a2[i] = dup2(af[i]);
            #pragma unroll
            for (int j = 0; j < TN / 2; j++) b2[j] = pk2(bf[2 * j], bf[2 * j + 1]);
            #pragma unroll
            for (int i = 0; i < TM; i++)
                #pragma unroll
                for (int j = 0; j < TN / 2; j++) fma2(acc[i][j], a2[i], b2[j]);
        }
        if (t + 1 < T) {
            stA(cur ^ 1); stB(cur ^ 1);
            __syncthreads();
            cur ^= 1;
        }
    }

    float as_r[TN], ad_r[TN];
    if constexpr (FUSE) {
        #pragma unroll
        for (int j = 0; j < TN; j++) {
            as_r[j] = __ldg(&av_s[colBase + tx * TN + j]);
            ad_r[j] = __ldg(&av_d[colBase + tx * TN + j]);
        }
    }
    constexpr int GROUP = BN / TN;   // 16 for our configs
    #pragma unroll
    for (int i = 0; i < TM; i++) {
        int gr = rowBase + ty * TM + i;
        float vbuf[TN];
        #pragma unroll
        for (int j = 0; j < TN / 2; j++) unpk2(vbuf[2 * j], vbuf[2 * j + 1], acc[i][j]);
        if (gr < M) {
            #pragma unroll
            for (int j = 0; j < TN; j += 4)
                *(float4*)&C[(size_t)gr * N + colBase + tx * TN + j] =
                    make_float4(vbuf[j], vbuf[j + 1], vbuf[j + 2], vbuf[j + 3]);
        }
        if constexpr (FUSE) {
            float ps = 0.f, pd = 0.f;
            #pragma unroll
            for (int j = 0; j < TN; j++) {
                ps = fmaf(vbuf[j], as_r[j], ps);
                pd = fmaf(vbuf[j], ad_r[j], pd);
            }
            #pragma unroll
            for (int off = GROUP / 2; off; off >>= 1) {
                ps += __shfl_xor_sync(0xffffffffu, ps, off);
                pd += __shfl_xor_sync(0xffffffffu, pd, off);
            }
            if (tx == 0 && gr < M) {
                atomicAdd(&dot_s[gr], ps);
                atomicAdd(&dot_d[gr], pd);
            }
        }
    }
}

// ---------------- CSR build ----------------
__global__ void k_cnt_all(const int* __restrict__ hn, const int* __restrict__ he,
                          const int* __restrict__ ei) {
    int i = blockIdx.x * blockDim.x + threadIdx.x;
    if (i < N_PAIRS) {
        atomicAdd(&c_cnt_nd[hn[i]], 1);
        atomicAdd(&c_cnt_he[he[i]], 1);
    }
    int t = i - N_PAIRS;
    if (t >= 0 && t < E2) {
        int d = (t < E_EDGES) ? ei[E_EDGES + t] : (t - E_EDGES);
        atomicAdd(&c_cnt_g[d], 1);
    }
}

__device__ void scan_block(const int* __restrict__ in, int* __restrict__ off,
                           int* __restrict__ cur, int n) {
    const int tid = threadIdx.x;
    const int lane = tid & 31, wid = tid >> 5;
    __shared__ int wsums[32];
    __shared__ int s_tot;
    int carry = 0;
    for (int base = 0; base < n; base += 8192) {
        int i0 = base + tid * 8;
        int o[8], v[8];
        #pragma unroll
        for (int j = 0; j < 8; j++) o[j] = (i0 + j < n) ? in[i0 + j] : 0;
        v[0] = o[0];
        #pragma unroll
        for (int j = 1; j < 8; j++) v[j] = v[j - 1] + o[j];
        int tsum = v[7];
        int x = tsum;
        #pragma unroll
        for (int d = 1; d < 32; d <<= 1) {
            int y = __shfl_up_sync(0xffffffffu, x, d);
            if (lane >= d) x += y;
        }
        if (lane == 31) wsums[wid] = x;
        __syncthreads();
        if (wid == 0) {
            int y = wsums[lane], z = y;
            #pragma unroll
            for (int d = 1; d < 32; d <<= 1) {
                int u = __shfl_up_sync(0xffffffffu, z, d);
                if (lane >= d) z += u;
            }
            if (lane == 31) s_tot = z;
            wsums[lane] = z - y;
        }
        __syncthreads();
        int offv = carry + wsums[wid] + (x - tsum);
        #pragma unroll
        for (int j = 0; j < 8; j++) {
            if (i0 + j < n) {
                int e = offv + v[j] - o[j];
                off[i0 + j] = e;
                cur[i0 + j] = e;
            }
        }
        carry += s_tot;
        __syncthreads();
    }
}
__global__ void __launch_bounds__(1024) k_scan3() {
    if (blockIdx.x == 0)      scan_block(c_cnt_he, c_off_he, c_cur_he, N_HE);
    else if (blockIdx.x == 1) scan_block(c_cnt_nd, c_off_nd, c_cur_nd, N_NODES);
    else                      scan_block(c_cnt_g,  c_off_g,  c_cur_g,  N_NODES);
}

__global__ void k_fill_all(const int* __restrict__ hn, const int* __restrict__ he,
                           const int* __restrict__ ei) {
    int i = blockIdx.x * blockDim.x + threadIdx.x;
    if (i < N_PAIRS) {
        int n = hn[i], e = he[i];
        c_val_he[atomicAdd(&c_cur_he[e], 1)] = n;
        c_val_nd[atomicAdd(&c_cur_nd[n], 1)] = e;
    }
    int t = i - N_PAIRS;
    if (t >= 0 && t < E2) {
        int s, d;
        if (t < E_EDGES) { s = ei[t]; d = ei[E_EDGES + t]; } else { s = d = t - E_EDGES; }
        c_val_g[atomicAdd(&c_cur_g[d], 1)] = s;
    }
}

// ---------------- hypergraph conv ----------------
// gather raw x (128-dim) per hyperedge, scale by Binv (GEMM applied after, by linearity)
__global__ void k_hc_edge_gather128(const float* __restrict__ x) {
    int gw = (blockIdx.x * blockDim.x + threadIdx.x) >> 5;
    int lane = threadIdx.x & 31;
    if (gw >= N_HE) return;
    int deg = c_cnt_he[gw], start = c_off_he[gw];
    float4 a = {0, 0, 0, 0};
    int i = 0;
    for (; i + 4 <= deg; i += 4) {
        int n0 = c_val_he[start + i],     n1 = c_val_he[start + i + 1];
        int n2 = c_val_he[start + i + 2], n3 = c_val_he[start + i + 3];
        float4 x0 = ((const float4*)(x + (size_t)n0 * 128))[lane];
        float4 x1 = ((const float4*)(x + (size_t)n1 * 128))[lane];
        float4 x2 = ((const float4*)(x + (size_t)n2 * 128))[lane];
        float4 x3 = ((const float4*)(x + (size_t)n3 * 128))[lane];
        f4add(a, x0); f4add(a, x1); f4add(a, x2); f4add(a, x3);
    }
    for (; i < deg; i++) {
        f4add(a, ((const float4*)(x + (size_t)c_val_he[start + i] * 128))[lane]);
    }
    float binv = deg > 0 ? 1.f / (float)deg : 0.f;
    a.x *= binv; a.y *= binv; a.z *= binv; a.w *= binv;
    ((float4*)(g_h0 + (size_t)gw * 128))[lane] = a;
}
// node gather over 256-dim hyperedge messages + Dinv + bias + relu
__global__ void k_hc_node_gather(const float* __restrict__ b1) {
    int gw = (blockIdx.x * blockDim.x + threadIdx.x) >> 5;
    int lane = threadIdx.x & 31;
    if (gw >= N_NODES) return;
    int deg = c_cnt_nd[gw], start = c_off_nd[gw];
    float4 a0 = {0, 0, 0, 0}, a1 = {0, 0, 0, 0};
    int i = 0;
    for (; i + 4 <= deg; i += 4) {
        const float4* p0 = (const float4*)(g_m + (size_t)c_val_nd[start + i] * 256);
        const float4* p1 = (const float4*)(g_m + (size_t)c_val_nd[start + i + 1] * 256);
        const float4* p2 = (const float4*)(g_m + (size_t)c_val_nd[start + i + 2] * 256);
        const float4* p3 = (const float4*)(g_m + (size_t)c_val_nd[start + i + 3] * 256);
        float4 x0a = p0[lane], x0b = p0[lane + 32];
        float4 x1a = p1[lane], x1b = p1[lane + 32];
        float4 x2a = p2[lane], x2b = p2[lane + 32];
        float4 x3a = p3[lane], x3b = p3[lane + 32];
        f4add(a0, x0a); f4add(a1, x0b);
        f4add(a0, x1a); f4add(a1, x1b);
        f4add(a0, x2a); f4add(a1, x2b);
        f4add(a0, x3a); f4add(a1, x3b);
    }
    for (; i < deg; i++) {
        const float4* p0 = (const float4*)(g_m + (size_t)c_val_nd[start + i] * 256);
        f4add(a0, p0[lane]); f4add(a1, p0[lane + 32]);
    }
    float dinv = deg > 0 ? 1.f / (float)deg : 0.f;
    float4 bb0 = __ldg((const float4*)b1 + lane);
    float4 bb1 = __ldg((const float4*)b1 + lane + 32);
    float4 r0, r1;
    r0.x = fmaxf(a0.x * dinv + bb0.x, 0.f); r0.y = fmaxf(a0.y * dinv + bb0.y, 0.f);
    r0.z = fmaxf(a0.z * dinv + bb0.z, 0.f); r0.w = fmaxf(a0.w * dinv + bb0.w, 0.f);
    r1.x = fmaxf(a1.x * dinv + bb1.x, 0.f); r1.y = fmaxf(a1.y * dinv + bb1.y, 0.f);
    r1.z = fmaxf(a1.z * dinv + bb1.z, 0.f); r1.w = fmaxf(a1.w * dinv + bb1.w, 0.f);
    float4* dst = (float4*)(g_h1 + (size_t)gw * 256);
    dst[lane] = r0;
    dst[lane + 32] = r1;
}

// ---------------- GAT aggregation (dots already computed in GEMM epilogue) --------
template <int C>
__global__ void k_gat_aggr(const float* __restrict__ bias, float* __restrict__ dst) {
    int gw = (blockIdx.x * blockDim.x + threadIdx.x) >> 5;
    int lane = threadIdx.x & 31;
    if (gw >= N_NODES) return;
    int deg = c_cnt_g[gw], start = c_off_g[gw];
    float adst = g_ad[gw];
    float mx = -1e30f;
    for (int i = lane; i < deg; i += 32)
        mx = fmaxf(mx, lrelu02(g_as[c_val_g[start + i]] + adst));
    #pragma unroll
    for (int off = 16; off; off >>= 1)
        mx = fmaxf(mx, __shfl_xor_sync(0xffffffffu, mx, off));
    float sm = 0.f;
    for (int i = lane; i < deg; i += 32)
        sm += expf(lrelu02(g_as[c_val_g[start + i]] + adst) - mx);
    #pragma unroll
    for (int off = 16; off; off >>= 1)
        sm += __shfl_xor_sync(0xffffffffu, sm, off);
    float inv = 1.f / (sm + 1e-16f);
    if constexpr (C == 256) {
        float4 a0 = {0, 0, 0, 0}, a1 = {0, 0, 0, 0};
        int i = 0;
        for (; i + 4 <= deg; i += 4) {
            int s0 = c_val_g[start + i],     s1 = c_val_g[start + i + 1];
            int s2 = c_val_g[start + i + 2], s3 = c_val_g[start + i + 3];
            float w0 = expf(lrelu02(g_as[s0] + adst) - mx) * inv;
            float w1 = expf(lrelu02(g_as[s1] + adst) - mx) * inv;
            float w2 = expf(lrelu02(g_as[s2] + adst) - mx) * inv;
            float w3 = expf(lrelu02(g_as[s3] + adst) - mx) * inv;
            const float4* p0 = (const float4*)(g_hg + (size_t)s0 * 256);
            const float4* p1 = (const float4*)(g_hg + (size_t)s1 * 256);
            const float4* p2 = (const float4*)(g_hg + (size_t)s2 * 256);
            const float4* p3 = (const float4*)(g_hg + (size_t)s3 * 256);
            float4 x0a = p0[lane], x0b = p0[lane + 32];
            float4 x1a = p1[lane], x1b = p1[lane + 32];
            float4 x2a = p2[lane], x2b = p2[lane + 32];
            float4 x3a = p3[lane], x3b = p3[lane + 32];
            f4fma(a0, w0, x0a); f4fma(a1, w0, x0b);
            f4fma(a0, w1, x1a); f4fma(a1, w1, x1b);
            f4fma(a0, w2, x2a); f4fma(a1, w2, x2b);
            f4fma(a0, w3, x3a); f4fma(a1, w3, x3b);
        }
        for (; i < deg; i++) {
            int s0 = c_val_g[start + i];
            float w0 = expf(lrelu02(g_as[s0] + adst) - mx) * inv;
            const float4* p0 = (const float4*)(g_hg + (size_t)s0 * 256);
            f4fma(a0, w0, p0[lane]); f4fma(a1, w0, p0[lane + 32]);
        }
        float4 bb0 = __ldg((const float4*)bias + lane);
        float4 bb1 = __ldg((const float4*)bias + lane + 32);
        float4 r0, r1;
        r0.x = fmaxf(a0.x + bb0.x, 0.f); r0.y = fmaxf(a0.y + bb0.y, 0.f);
        r0.z = fmaxf(a0.z + bb0.z, 0.f); r0.w = fmaxf(a0.w + bb0.w, 0.f);
        r1.x = fmaxf(a1.x + bb1.x, 0.f); r1.y = fmaxf(a1.y + bb1.y, 0.f);
        r1.z = fmaxf(a1.z + bb1.z, 0.f); r1.w = fmaxf(a1.w + bb1.w, 0.f);
        float4* o = (float4*)(dst + (size_t)gw * 256);
        o[lane] = r0;
        o[lane + 32] = r1;
    } else {
        float2 acc = {0, 0};
        int i = 0;
        for (; i + 4 <= deg; i += 4) {
            int s0 = c_val_g[start + i],     s1 = c_val_g[start + i + 1];
            int s2 = c_val_g[start + i + 2], s3 = c_val_g[start + i + 3];
            float w0 = expf(lrelu02(g_as[s0] + adst) - mx) * inv;
            float w1 = expf(lrelu02(g_as[s1] + adst) - mx) * inv;
            float w2 = expf(lrelu02(g_as[s2] + adst) - mx) * inv;
            float w3 = expf(lrelu02(g_as[s3] + adst) - mx) * inv;
            float2 x0 = *(const float2*)(g_hg + (size_t)s0 * 64 + 2 * lane);
            float2 x1 = *(const float2*)(g_hg + (size_t)s1 * 64 + 2 * lane);
            float2 x2 = *(const float2*)(g_hg + (size_t)s2 * 64 + 2 * lane);
            float2 x3 = *(const float2*)(g_hg + (size_t)s3 * 64 + 2 * lane);
            acc.x = fmaf(w0, x0.x, acc.x); acc.y = fmaf(w0, x0.y, acc.y);
            acc.x = fmaf(w1, x1.x, acc.x); acc.y = fmaf(w1, x1.y, acc.y);
            acc.x = fmaf(w2, x2.x, acc.x); acc.y = fmaf(w2, x2.y, acc.y);
            acc.x = fmaf(w3, x3.x, acc.x); acc.y = fmaf(w3, x3.y, acc.y);
        }
        for (; i < deg; i++) {
            int s0 = c_val_g[start + i];
            float w0 = expf(lrelu02(g_as[s0] + adst) - mx) * inv;
            float2 x0 = *(const float2*)(g_hg + (size_t)s0 * 64 + 2 * lane);
            acc.x = fmaf(w0, x0.x, acc.x); acc.y = fmaf(w0, x0.y, acc.y);
        }
        float2 bb = *(const float2*)(bias + 2 * lane);
        float2 r;
        r.x = fmaxf(acc.x + bb.x, 0.f);
        r.y = fmaxf(acc.y + bb.y, 0.f);
        *(float2*)(dst + (size_t)gw * 64 + 2 * lane) = r;
    }
}

// ---------------- decode MLP (warp per edge, f32x2, channel pairs per lane) --------
#define DEC_WARPS 8
__global__ __launch_bounds__(256)
void decode_kernel(const int* __restrict__ eli,
                   const float* __restrict__ Wm1, const float* __restrict__ bm1,
                   const float* __restrict__ Wm2, const float* __restrict__ bm2,
                   const float* __restrict__ Wm3, const float* __restrict__ bm3,
                   const float* __restrict__ Wm4, const float* __restrict__ bm4,
                   float* __restrict__ out) {
    __shared__ float sW1[128 * 64];
    __shared__ float sW2[64 * 64];
    __shared__ float sW3[64 * 64];
    __shared__ float es[DEC_WARPS][128];
    __shared__ float hs[DEC_WARPS][64];
    const int lane = threadIdx.x & 31;
    const int w = threadIdx.x >> 5;
    for (int i = threadIdx.x; i < 128 * 64; i += blockDim.x) sW1[i] = Wm1[i];
    for (int i = threadIdx.x; i < 64 * 64; i += blockDim.x) { sW2[i] = Wm2[i]; sW3[i] = Wm3[i]; }
    __syncthreads();
    int gw = blockIdx.x * DEC_WARPS + w;
    int stride = gridDim.x * DEC_WARPS;
    const int c2 = 2 * lane;
    for (int t = gw; t < L_EDGES; t += stride) {
        int s = eli[t], d = eli[L_EDGES + t];
        *(float2*)&es[w][c2]      = *(const float2*)&g_z[(size_t)s * 64 + c2];
        *(float2*)&es[w][64 + c2] = *(const float2*)&g_z[(size_t)d * 64 + c2];
        __syncwarp();
        {
            float2 bb = *(const float2*)&bm1[c2];
            u64 a0 = pk2(bb.x, bb.y), a1 = 0ULL, a2 = 0ULL, a3 = 0ULL;
            #pragma unroll
            for (int k = 0; k < 128; k += 4) {
                float4 ev = *(const float4*)&es[w][k];
                float2 w0 = *(const float2*)&sW1[(k + 0) * 64 + c2];
                float2 w1 = *(const float2*)&sW1[(k + 1) * 64 + c2];
                float2 w2 = *(const float2*)&sW1[(k + 2) * 64 + c2];
                float2 w3 = *(const float2*)&sW1[(k + 3) * 64 + c2];
                fma2(a0, dup2(ev.x), pk2(w0.x, w0.y));
                fma2(a1, dup2(ev.y), pk2(w1.x, w1.y));
                fma2(a2, dup2(ev.z), pk2(w2.x, w2.y));
                fma2(a3, dup2(ev.w), pk2(w3.x, w3.y));
            }
            add2(a0, a1); add2(a2, a3); add2(a0, a2);
            float r0, r1; unpk2(r0, r1, a0);
            __syncwarp();
            hs[w][c2] = fmaxf(r0, 0.f); hs[w][c2 + 1] = fmaxf(r1, 0.f);
            __syncwarp();
        }
        #pragma unroll
        for (int L = 0; L < 2; L++) {
            const float* Wl = L == 0 ? sW2 : sW3;
            const float* bl = L == 0 ? bm2 : bm3;
            float2 bb = *(const float2*)&bl[c2];
            u64 a0 = pk2(bb.x, bb.y), a1 = 0ULL, a2 = 0ULL, a3 = 0ULL;
            #pragma unroll
            for (int k = 0; k < 64; k += 4) {
                float4 ev = *(const float4*)&hs[w][k];
                float2 w0 = *(const float2*)&Wl[(k + 0) * 64 + c2];
                float2 w1 = *(const float2*)&Wl[(k + 1) * 64 + c2];
                float2 w2 = *(const float2*)&Wl[(k + 2) * 64 + c2];
                float2 w3 = *(const float2*)&Wl[(k + 3) * 64 + c2];
                fma2(a0, dup2(ev.x), pk2(w0.x, w0.y));
                fma2(a1, dup2(ev.y), pk2(w1.x, w1.y));
                fma2(a2, dup2(ev.z), pk2(w2.x, w2.y));
                fma2(a3, dup2(ev.w), pk2(w3.x, w3.y));
            }
            add2(a0, a1); add2(a2, a3); add2(a0, a2);
            float r0, r1; unpk2(r0, r1, a0);
            __syncwarp();
            hs[w][c2] = fmaxf(r0, 0.f); hs[w][c2 + 1] = fmaxf(r1, 0.f);
            __syncwarp();
        }
        float2 hv = *(const float2*)&hs[w][c2];
        float o0 = hv.x * __ldg(&Wm4[c2 * 3 + 0]) + hv.y * __ldg(&Wm4[(c2 + 1) * 3 + 0]);
        float o1 = hv.x * __ldg(&Wm4[c2 * 3 + 1]) + hv.y * __ldg(&Wm4[(c2 + 1) * 3 + 1]);
        float o2 = hv.x * __ldg(&Wm4[c2 * 3 + 2]) + hv.y * __ldg(&Wm4[(c2 + 1) * 3 + 2]);
        #pragma unroll
        for (int off = 16; off; off >>= 1) {
            o0 += __shfl_down_sync(0xffffffffu, o0, off);
            o1 += __shfl_down_sync(0xffffffffu, o1, off);
            o2 += __shfl_down_sync(0xffffffffu, o2, off);
        }
        if (lane == 0) {
            o0 += __ldg(&bm4[0]); o1 += __ldg(&bm4[1]); o2 += __ldg(&bm4[2]);
            int   idx  = 0;
            float best = o0;
            if (o1 > best) { best = o1; idx = 1; }
            if (o2 > best) { best = o2; idx = 2; }
            out[t]           = (float)idx;
            out[L_EDGES + t] = best;
            out[2 * L_EDGES + t * 3 + 0] = o0;
            out[2 * L_EDGES + t * 3 + 1] = o1;
            out[2 * L_EDGES + t * 3 + 2] = o2;
        }
        __syncwarp();
    }
}

// ---------------- host launch ----------------
static inline int cdiv(int a, int b) { return (a + b - 1) / b; }

extern "C" void kernel_launch(void* const* d_in, const int* in_sizes, int n_in,
                              void* d_out, int out_size) {
    const float* x   = (const float*)d_in[0];
    const int*   ei  = (const int*)d_in[1];
    const int*   hn  = (const int*)d_in[2];
    const int*   he  = (const int*)d_in[3];
    const int*   eli = (const int*)d_in[4];
    const float* W1  = (const float*)d_in[5];
    const float* b1  = (const float*)d_in[6];
    const float* W2  = (const float*)d_in[7];
    const float* a2s = (const float*)d_in[8];
    const float* a2d = (const float*)d_in[9];
    const float* b2  = (const float*)d_in[10];
    const float* W3  = (const float*)d_in[11];
    const float* a3s = (const float*)d_in[12];
    const float* a3d = (const float*)d_in[13];
    const float* b3  = (const float*)d_in[14];
    const float* Wm1 = (const float*)d_in[15];
    const float* bm1 = (const float*)d_in[16];
    const float* Wm2 = (const float*)d_in[17];
    const float* bm2 = (const float*)d_in[18];
    const float* Wm3 = (const float*)d_in[19];
    const float* bm3 = (const float*)d_in[20];
    const float* Wm4 = (const float*)d_in[21];
    const float* bm4 = (const float*)d_in[22];
    float* out = (float*)d_out;

    void *p_cnt_he, *p_cnt_nd, *p_cnt_g, *p_h0, *p_h1, *p_hg, *p_z, *p_m, *p_as, *p_ad;
    cudaGetSymbolAddress(&p_cnt_he, c_cnt_he);
    cudaGetSymbolAddress(&p_cnt_nd, c_cnt_nd);
    cudaGetSymbolAddress(&p_cnt_g,  c_cnt_g);
    cudaGetSymbolAddress(&p_h0, g_h0);
    cudaGetSymbolAddress(&p_h1, g_h1);
    cudaGetSymbolAddress(&p_hg, g_hg);
    cudaGetSymbolAddress(&p_z,  g_z);
    cudaGetSymbolAddress(&p_m,  g_m);
    cudaGetSymbolAddress(&p_as, g_as);
    cudaGetSymbolAddress(&p_ad, g_ad);

    const int TB = 256;

    // ===== CSR builds =====
    cudaMemsetAsync(p_cnt_he, 0, sizeof(int) * N_HE, 0);
    cudaMemsetAsync(p_cnt_nd, 0, sizeof(int) * N_NODES, 0);
    cudaMemsetAsync(p_cnt_g,  0, sizeof(int) * N_NODES, 0);
    k_cnt_all<<<cdiv(N_PAIRS + E2, TB), TB>>>(hn, he, ei);
    k_scan3<<<3, 1024>>>();
    k_fill_all<<<cdiv(N_PAIRS + E2, TB), TB>>>(hn, he, ei);

    // ===== hypergraph conv: gather x (128d) -> GEMM on hyperedges -> node gather =====
    k_hc_edge_gather128<<<cdiv(N_HE * 32, TB), TB>>>(x);
    sgemm<128, 128, 16, 8, 8, false><<<dim3(2, cdiv(N_HE, 128)), 256>>>(
        (float*)p_h0, W1, (float*)p_m, N_HE, 256, 128, nullptr, nullptr, nullptr, nullptr);
    k_hc_node_gather<<<cdiv(N_NODES * 32, TB), TB>>>(b1);

    // ===== GAT layer 1 (256 -> 256), dots fused into GEMM epilogue =====
    cudaMemsetAsync(p_as, 0, sizeof(float) * N_NODES, 0);
    cudaMemsetAsync(p_ad, 0, sizeof(float) * N_NODES, 0);
    sgemm<128, 128, 16, 8, 8, true><<<dim3(2, cdiv(N_NODES, 128)), 256>>>(
        (float*)p_h1, W2, (float*)p_hg, N_NODES, 256, 256, a2s, a2d, (float*)p_as, (float*)p_ad);
    k_gat_aggr<256><<<cdiv(N_NODES * 32, TB), TB>>>(b2, (float*)p_h1);

    // ===== GAT layer 2 (256 -> 64), dots fused =====
    cudaMemsetAsync(p_as, 0, sizeof(float) * N_NODES, 0);
    cudaMemsetAsync(p_ad, 0, sizeof(float) * N_NODES, 0);
    sgemm<128, 64, 16, 8, 4, true><<<dim3(1, cdiv(N_NODES, 128)), 256>>>(
        (float*)p_h1, W3, (float*)p_hg, N_NODES, 64, 256, a3s, a3d, (float*)p_as, (float*)p_ad);
    k_gat_aggr<64><<<cdiv(N_NODES * 32, TB), TB>>>(b3, (float*)p_z);

    // ===== decode MLP =====
    decode_kernel<<<740, TB>>>(eli, Wm1, bm1, Wm2, bm2, Wm3, bm3, Wm4, bm4, out);
}

// round 7
// speedup vs baseline: 1.0436x; 1.0436x over previous
#include <cuda_runtime.h>
#include <math.h>

#define N_NODES   50000
#define N_HE      20000
#define N_PAIRS   400000
#define E_EDGES   800000
#define E2        (E_EDGES + N_NODES)
#define L_EDGES   100000

// ---------------- scratch (device globals; no runtime allocation) ----------------
__device__ float g_h0[N_NODES * 256];   // hconv: m128 staging; GAT: logit staging t[]
__device__ float g_m [N_HE    * 256];   // hyperedge messages post-GEMM
__device__ float g_h1[N_NODES * 256];   // activations (reused across layers)
__device__ float g_hg[N_NODES * 256];   // GEMM output features
__device__ float g_as[N_NODES];
__device__ float g_ad[N_NODES];
__device__ float g_z [N_NODES * 64];

__device__ int c_cnt_he[N_HE],    c_off_he[N_HE],    c_cur_he[N_HE],    c_val_he[N_PAIRS];
__device__ int c_cnt_nd[N_NODES], c_off_nd[N_NODES], c_cur_nd[N_NODES], c_val_nd[N_PAIRS];
__device__ int c_cnt_g [N_NODES], c_off_g [N_NODES], c_cur_g [N_NODES], c_val_g [E2];

typedef unsigned long long u64;

__device__ __forceinline__ float lrelu02(float x) { return x > 0.f ? x : 0.2f * x; }
__device__ __forceinline__ void f4add(float4& a, const float4 b) {
    a.x += b.x; a.y += b.y; a.z += b.z; a.w += b.w;
}
__device__ __forceinline__ void f4fma(float4& a, float w, const float4 b) {
    a.x = fmaf(w, b.x, a.x); a.y = fmaf(w, b.y, a.y);
    a.z = fmaf(w, b.z, a.z); a.w = fmaf(w, b.w, a.w);
}
// ---- packed fp32x2 (Blackwell FFMA2) ----
__device__ __forceinline__ u64 pk2(float lo, float hi) {
    u64 r; asm("mov.b64 %0, {%1, %2};" : "=l"(r) : "f"(lo), "f"(hi)); return r;
}
__device__ __forceinline__ u64 dup2(float x) { return pk2(x, x); }
__device__ __forceinline__ void unpk2(float& lo, float& hi, u64 v) {
    asm("mov.b64 {%0, %1}, %2;" : "=f"(lo), "=f"(hi) : "l"(v));
}
__device__ __forceinline__ void fma2(u64& d, u64 a, u64 b) {
    asm("fma.rn.f32x2 %0, %1, %2, %0;" : "+l"(d) : "l"(a), "l"(b));
}
__device__ __forceinline__ void add2(u64& d, u64 a) {
    asm("add.rn.f32x2 %0, %0, %1;" : "+l"(d) : "l"(a));
}

// ---------------- GEMM: C[M,N] = A[M,K] @ B[K,N], fp32, f32x2 core, double-buffered ----
template<int BM, int BN, int BK, int TM, int TN>
__global__ void __launch_bounds__((BM / TM) * (BN / TN))
sgemm(const float* __restrict__ A, const float* __restrict__ B, float* __restrict__ C,
      int M, int N, int K) {
    constexpr int NT = (BM / TM) * (BN / TN);
    constexpr int LA = BM * BK / 4 / NT;
    constexpr int LB = BK * BN / 4 / NT;
    __shared__ float As[2][BK][BM + 4];
    __shared__ float Bs[2][BK][BN];
    const int tid = threadIdx.x;
    const int tx = tid % (BN / TN);
    const int ty = tid / (BN / TN);
    const int rowBase = blockIdx.y * BM, colBase = blockIdx.x * BN;
    float4 ra[LA], rb[LB];

    auto loadA = [&](int k0) {
        #pragma unroll
        for (int s = 0; s < LA; s++) {
            int f = tid + s * NT;
            int r = f / (BK / 4), c = (f % (BK / 4)) * 4;
            int gr = rowBase + r;
            ra[s] = (gr < M) ? *(const float4*)&A[(size_t)gr * K + k0 + c]
                             : make_float4(0.f, 0.f, 0.f, 0.f);
        }
    };
    auto loadB = [&](int k0) {
        #pragma unroll
        for (int s = 0; s < LB; s++) {
            int f = tid + s * NT;
            int r = f / (BN / 4), c = (f % (BN / 4)) * 4;
            rb[s] = *(const float4*)&B[(size_t)(k0 + r) * N + colBase + c];
        }
    };
    auto stA = [&](int buf) {
        #pragma unroll
        for (int s = 0; s < LA; s++) {
            int f = tid + s * NT;
            int r = f / (BK / 4), c = (f % (BK / 4)) * 4;
            As[buf][c + 0][r] = ra[s].x; As[buf][c + 1][r] = ra[s].y;
            As[buf][c + 2][r] = ra[s].z; As[buf][c + 3][r] = ra[s].w;
        }
    };
    auto stB = [&](int buf) {
        #pragma unroll
        for (int s = 0; s < LB; s++) {
            int f = tid + s * NT;
            int r = f / (BN / 4), c = (f % (BN / 4)) * 4;
            *(float4*)&Bs[buf][r][c] = rb[s];
        }
    };

    u64 acc[TM][TN / 2];
    #pragma unroll
    for (int i = 0; i < TM; i++)
        #pragma unroll
        for (int j = 0; j < TN / 2; j++) acc[i][j] = 0ULL;

    loadA(0); loadB(0); stA(0); stB(0);
    __syncthreads();
    const int T = K / BK;
    int cur = 0;
    for (int t = 0; t < T; t++) {
        if (t + 1 < T) { loadA((t + 1) * BK); loadB((t + 1) * BK); }
        #pragma unroll
        for (int k = 0; k < BK; k++) {
            float af[TM], bf[TN];
            #pragma unroll
            for (int i = 0; i < TM; i += 4)
                *(float4*)&af[i] = *(const float4*)&As[cur][k][ty * TM + i];
            #pragma unroll
            for (int j = 0; j < TN; j += 4)
                *(float4*)&bf[j] = *(const float4*)&Bs[cur][k][tx * TN + j];
            u64 a2[TM], b2[TN / 2];
            #pragma unroll
            for (int i = 0; i < TM; i++) a2[i] = dup2(af[i]);
            #pragma unroll
            for (int j = 0; j < TN / 2; j++) b2[j] = pk2(bf[2 * j], bf[2 * j + 1]);
            #pragma unroll
            for (int i = 0; i < TM; i++)
                #pragma unroll
                for (int j = 0; j < TN / 2; j++) fma2(acc[i][j], a2[i], b2[j]);
        }
        if (t + 1 < T) {
            stA(cur ^ 1); stB(cur ^ 1);
            __syncthreads();
            cur ^= 1;
        }
    }
    #pragma unroll
    for (int i = 0; i < TM; i++) {
        int gr = rowBase + ty * TM + i;
        if (gr < M) {
            #pragma unroll
            for (int j = 0; j < TN / 4; j++) {
                float4 v;
                unpk2(v.x, v.y, acc[i][2 * j]);
                unpk2(v.z, v.w, acc[i][2 * j + 1]);
                *(float4*)&C[(size_t)gr * N + colBase + tx * TN + 4 * j] = v;
            }
        }
    }
}

// ---------------- CSR build ----------------
__global__ void k_cnt_all(const int* __restrict__ hn, const int* __restrict__ he,
                          const int* __restrict__ ei) {
    int i = blockIdx.x * blockDim.x + threadIdx.x;
    if (i < N_PAIRS) {
        atomicAdd(&c_cnt_nd[hn[i]], 1);
        atomicAdd(&c_cnt_he[he[i]], 1);
    }
    int t = i - N_PAIRS;
    if (t >= 0 && t < E2) {
        int d = (t < E_EDGES) ? ei[E_EDGES + t] : (t - E_EDGES);
        atomicAdd(&c_cnt_g[d], 1);
    }
}

__device__ void scan_block(const int* __restrict__ in, int* __restrict__ off,
                           int* __restrict__ cur, int n) {
    const int tid = threadIdx.x;
    const int lane = tid & 31, wid = tid >> 5;
    __shared__ int wsums[32];
    __shared__ int s_tot;
    int carry = 0;
    for (int base = 0; base < n; base += 8192) {
        int i0 = base + tid * 8;
        int o[8], v[8];
        #pragma unroll
        for (int j = 0; j < 8; j++) o[j] = (i0 + j < n) ? in[i0 + j] : 0;
        v[0] = o[0];
        #pragma unroll
        for (int j = 1; j < 8; j++) v[j] = v[j - 1] + o[j];
        int tsum = v[7];
        int x = tsum;
        #pragma unroll
        for (int d = 1; d < 32; d <<= 1) {
            int y = __shfl_up_sync(0xffffffffu, x, d);
            if (lane >= d) x += y;
        }
        if (lane == 31) wsums[wid] = x;
        __syncthreads();
        if (wid == 0) {
            int y = wsums[lane], z = y;
            #pragma unroll
            for (int d = 1; d < 32; d <<= 1) {
                int u = __shfl_up_sync(0xffffffffu, z, d);
                if (lane >= d) z += u;
            }
            if (lane == 31) s_tot = z;
            wsums[lane] = z - y;
        }
        __syncthreads();
        int offv = carry + wsums[wid] + (x - tsum);
        #pragma unroll
        for (int j = 0; j < 8; j++) {
            if (i0 + j < n) {
                int e = offv + v[j] - o[j];
                off[i0 + j] = e;
                cur[i0 + j] = e;
            }
        }
        carry += s_tot;
        __syncthreads();
    }
}
__global__ void __launch_bounds__(1024) k_scan3() {
    if (blockIdx.x == 0)      scan_block(c_cnt_he, c_off_he, c_cur_he, N_HE);
    else if (blockIdx.x == 1) scan_block(c_cnt_nd, c_off_nd, c_cur_nd, N_NODES);
    else                      scan_block(c_cnt_g,  c_off_g,  c_cur_g,  N_NODES);
}

__global__ void k_fill_all(const int* __restrict__ hn, const int* __restrict__ he,
                           const int* __restrict__ ei) {
    int i = blockIdx.x * blockDim.x + threadIdx.x;
    if (i < N_PAIRS) {
        int n = hn[i], e = he[i];
        c_val_he[atomicAdd(&c_cur_he[e], 1)] = n;
        c_val_nd[atomicAdd(&c_cur_nd[n], 1)] = e;
    }
    int t = i - N_PAIRS;
    if (t >= 0 && t < E2) {
        int s, d;
        if (t < E_EDGES) { s = ei[t]; d = ei[E_EDGES + t]; } else { s = d = t - E_EDGES; }
        c_val_g[atomicAdd(&c_cur_g[d], 1)] = s;
    }
}

// ---------------- hypergraph conv ----------------
__global__ void k_hc_edge_gather128(const float* __restrict__ x) {
    int gw = (blockIdx.x * blockDim.x + threadIdx.x) >> 5;
    int lane = threadIdx.x & 31;
    if (gw >= N_HE) return;
    int deg = c_cnt_he[gw], start = c_off_he[gw];
    float4 a = {0, 0, 0, 0};
    int i = 0;
    for (; i + 4 <= deg; i += 4) {
        int n0 = c_val_he[start + i],     n1 = c_val_he[start + i + 1];
        int n2 = c_val_he[start + i + 2], n3 = c_val_he[start + i + 3];
        float4 x0 = ((const float4*)(x + (size_t)n0 * 128))[lane];
        float4 x1 = ((const float4*)(x + (size_t)n1 * 128))[lane];
        float4 x2 = ((const float4*)(x + (size_t)n2 * 128))[lane];
        float4 x3 = ((const float4*)(x + (size_t)n3 * 128))[lane];
        f4add(a, x0); f4add(a, x1); f4add(a, x2); f4add(a, x3);
    }
    for (; i < deg; i++) {
        f4add(a, ((const float4*)(x + (size_t)c_val_he[start + i] * 128))[lane]);
    }
    float binv = deg > 0 ? 1.f / (float)deg : 0.f;
    a.x *= binv; a.y *= binv; a.z *= binv; a.w *= binv;
    ((float4*)(g_h0 + (size_t)gw * 128))[lane] = a;
}
__global__ void k_hc_node_gather(const float* __restrict__ b1) {
    int gw = (blockIdx.x * blockDim.x + threadIdx.x) >> 5;
    int lane = threadIdx.x & 31;
    if (gw >= N_NODES) return;
    int deg = c_cnt_nd[gw], start = c_off_nd[gw];
    float4 a0 = {0, 0, 0, 0}, a1 = {0, 0, 0, 0};
    int i = 0;
    for (; i + 4 <= deg; i += 4) {
        const float4* p0 = (const float4*)(g_m + (size_t)c_val_nd[start + i] * 256);
        const float4* p1 = (const float4*)(g_m + (size_t)c_val_nd[start + i + 1] * 256);
        const float4* p2 = (const float4*)(g_m + (size_t)c_val_nd[start + i + 2] * 256);
        const float4* p3 = (const float4*)(g_m + (size_t)c_val_nd[start + i + 3] * 256);
        float4 x0a = p0[lane], x0b = p0[lane + 32];
        float4 x1a = p1[lane], x1b = p1[lane + 32];
        float4 x2a = p2[lane], x2b = p2[lane + 32];
        float4 x3a = p3[lane], x3b = p3[lane + 32];
        f4add(a0, x0a); f4add(a1, x0b);
        f4add(a0, x1a); f4add(a1, x1b);
        f4add(a0, x2a); f4add(a1, x2b);
        f4add(a0, x3a); f4add(a1, x3b);
    }
    for (; i < deg; i++) {
        const float4* p0 = (const float4*)(g_m + (size_t)c_val_nd[start + i] * 256);
        f4add(a0, p0[lane]); f4add(a1, p0[lane + 32]);
    }
    float dinv = deg > 0 ? 1.f / (float)deg : 0.f;
    float4 bb0 = __ldg((const float4*)b1 + lane);
    float4 bb1 = __ldg((const float4*)b1 + lane + 32);
    float4 r0, r1;
    r0.x = fmaxf(a0.x * dinv + bb0.x, 0.f); r0.y = fmaxf(a0.y * dinv + bb0.y, 0.f);
    r0.z = fmaxf(a0.z * dinv + bb0.z, 0.f); r0.w = fmaxf(a0.w * dinv + bb0.w, 0.f);
    r1.x = fmaxf(a1.x * dinv + bb1.x, 0.f); r1.y = fmaxf(a1.y * dinv + bb1.y, 0.f);
    r1.z = fmaxf(a1.z * dinv + bb1.z, 0.f); r1.w = fmaxf(a1.w * dinv + bb1.w, 0.f);
    float4* dst = (float4*)(g_h1 + (size_t)gw * 256);
    dst[lane] = r0;
    dst[lane + 32] = r1;
}

// ---------------- GAT ----------------
template <int C>
__global__ void k_dots(const float* __restrict__ a_s, const float* __restrict__ a_d) {
    int gw = (blockIdx.x * blockDim.x + threadIdx.x) >> 5;
    int lane = threadIdx.x & 31;
    if (gw >= N_NODES) return;
    float s0 = 0.f, s1 = 0.f;
    const float4* h = (const float4*)(g_hg + (size_t)gw * C);
    #pragma unroll
    for (int j = lane; j < C / 4; j += 32) {
        float4 v = h[j];
        float4 as4 = __ldg((const float4*)a_s + j);
        float4 ad4 = __ldg((const float4*)a_d + j);
        s0 += v.x * as4.x + v.y * as4.y + v.z * as4.z + v.w * as4.w;
        s1 += v.x * ad4.x + v.y * ad4.y + v.z * ad4.z + v.w * ad4.w;
    }
    #pragma unroll
    for (int off = 16; off; off >>= 1) {
        s0 += __shfl_down_sync(0xffffffffu, s0, off);
        s1 += __shfl_down_sync(0xffffffffu, s1, off);
    }
    if (lane == 0) { g_as[gw] = s0; g_ad[gw] = s1; }
}

// stage per-CSR-slot source attention values: t[e] = g_as[c_val_g[e]]
__global__ void k_gat_logits(float* __restrict__ t) {
    int e = blockIdx.x * blockDim.x + threadIdx.x;
    if (e < E2) t[e] = g_as[c_val_g[e]];
}

// warp per dst node: softmax over staged t[] (sequential reads) + weighted gather
template <int C>
__global__ void k_gat_aggr(const float* __restrict__ t,
                           const float* __restrict__ bias, float* __restrict__ dst) {
    int gw = (blockIdx.x * blockDim.x + threadIdx.x) >> 5;
    int lane = threadIdx.x & 31;
    if (gw >= N_NODES) return;
    int deg = c_cnt_g[gw], start = c_off_g[gw];
    float adst = g_ad[gw];
    float mx = -1e30f;
    for (int i = lane; i < deg; i += 32)
        mx = fmaxf(mx, lrelu02(t[start + i] + adst));
    #pragma unroll
    for (int off = 16; off; off >>= 1)
        mx = fmaxf(mx, __shfl_xor_sync(0xffffffffu, mx, off));
    float sm = 0.f;
    for (int i = lane; i < deg; i += 32)
        sm += expf(lrelu02(t[start + i] + adst) - mx);
    #pragma unroll
    for (int off = 16; off; off >>= 1)
        sm += __shfl_xor_sync(0xffffffffu, sm, off);
    float inv = 1.f / (sm + 1e-16f);
    if constexpr (C == 256) {
        float4 a0 = {0, 0, 0, 0}, a1 = {0, 0, 0, 0};
        int i = 0;
        for (; i + 4 <= deg; i += 4) {
            int s0 = c_val_g[start + i],     s1 = c_val_g[start + i + 1];
            int s2 = c_val_g[start + i + 2], s3 = c_val_g[start + i + 3];
            float w0 = expf(lrelu02(t[start + i] + adst) - mx) * inv;
            float w1 = expf(lrelu02(t[start + i + 1] + adst) - mx) * inv;
            float w2 = expf(lrelu02(t[start + i + 2] + adst) - mx) * inv;
            float w3 = expf(lrelu02(t[start + i + 3] + adst) - mx) * inv;
            const float4* p0 = (const float4*)(g_hg + (size_t)s0 * 256);
            const float4* p1 = (const float4*)(g_hg + (size_t)s1 * 256);
            const float4* p2 = (const float4*)(g_hg + (size_t)s2 * 256);
            const float4* p3 = (const float4*)(g_hg + (size_t)s3 * 256);
            float4 x0a = p0[lane], x0b = p0[lane + 32];
            float4 x1a = p1[lane], x1b = p1[lane + 32];
            float4 x2a = p2[lane], x2b = p2[lane + 32];
            float4 x3a = p3[lane], x3b = p3[lane + 32];
            f4fma(a0, w0, x0a); f4fma(a1, w0, x0b);
            f4fma(a0, w1, x1a); f4fma(a1, w1, x1b);
            f4fma(a0, w2, x2a); f4fma(a1, w2, x2b);
            f4fma(a0, w3, x3a); f4fma(a1, w3, x3b);
        }
        for (; i < deg; i++) {
            int s0 = c_val_g[start + i];
            float w0 = expf(lrelu02(t[start + i] + adst) - mx) * inv;
            const float4* p0 = (const float4*)(g_hg + (size_t)s0 * 256);
            f4fma(a0, w0, p0[lane]); f4fma(a1, w0, p0[lane + 32]);
        }
        float4 bb0 = __ldg((const float4*)bias + lane);
        float4 bb1 = __ldg((const float4*)bias + lane + 32);
        float4 r0, r1;
        r0.x = fmaxf(a0.x + bb0.x, 0.f); r0.y = fmaxf(a0.y + bb0.y, 0.f);
        r0.z = fmaxf(a0.z + bb0.z, 0.f); r0.w = fmaxf(a0.w + bb0.w, 0.f);
        r1.x = fmaxf(a1.x + bb1.x, 0.f); r1.y = fmaxf(a1.y + bb1.y, 0.f);
        r1.z = fmaxf(a1.z + bb1.z, 0.f); r1.w = fmaxf(a1.w + bb1.w, 0.f);
        float4* o = (float4*)(dst + (size_t)gw * 256);
        o[lane] = r0;
        o[lane + 32] = r1;
    } else {
        float2 acc = {0, 0};
        int i = 0;
        for (; i + 4 <= deg; i += 4) {
            int s0 = c_val_g[start + i],     s1 = c_val_g[start + i + 1];
            int s2 = c_val_g[start + i + 2], s3 = c_val_g[start + i + 3];
            float w0 = expf(lrelu02(t[start + i] + adst) - mx) * inv;
            float w1 = expf(lrelu02(t[start + i + 1] + adst) - mx) * inv;
            float w2 = expf(lrelu02(t[start + i + 2] + adst) - mx) * inv;
            float w3 = expf(lrelu02(t[start + i + 3] + adst) - mx) * inv;
            float2 x0 = *(const float2*)(g_hg + (size_t)s0 * 64 + 2 * lane);
            float2 x1 = *(const float2*)(g_hg + (size_t)s1 * 64 + 2 * lane);
            float2 x2 = *(const float2*)(g_hg + (size_t)s2 * 64 + 2 * lane);
            float2 x3 = *(const float2*)(g_hg + (size_t)s3 * 64 + 2 * lane);
            acc.x = fmaf(w0, x0.x, acc.x); acc.y = fmaf(w0, x0.y, acc.y);
            acc.x = fmaf(w1, x1.x, acc.x); acc.y = fmaf(w1, x1.y, acc.y);
            acc.x = fmaf(w2, x2.x, acc.x); acc.y = fmaf(w2, x2.y, acc.y);
            acc.x = fmaf(w3, x3.x, acc.x); acc.y = fmaf(w3, x3.y, acc.y);
        }
        for (; i < deg; i++) {
            int s0 = c_val_g[start + i];
            float w0 = expf(lrelu02(t[start + i] + adst) - mx) * inv;
            float2 x0 = *(const float2*)(g_hg + (size_t)s0 * 64 + 2 * lane);
            acc.x = fmaf(w0, x0.x, acc.x); acc.y = fmaf(w0, x0.y, acc.y);
        }
        float2 bb = *(const float2*)(bias + 2 * lane);
        float2 r;
        r.x = fmaxf(acc.x + bb.x, 0.f);
        r.y = fmaxf(acc.y + bb.y, 0.f);
        *(float2*)(dst + (size_t)gw * 64 + 2 * lane) = r;
    }
}

// ---------------- decode MLP (warp per edge, f32x2, channel pairs per lane) --------
#define DEC_WARPS 8
__global__ __launch_bounds__(256)
void decode_kernel(const int* __restrict__ eli,
                   const float* __restrict__ Wm1, const float* __restrict__ bm1,
                   const float* __restrict__ Wm2, const float* __restrict__ bm2,
                   const float* __restrict__ Wm3, const float* __restrict__ bm3,
                   const float* __restrict__ Wm4, const float* __restrict__ bm4,
                   float* __restrict__ out) {
    __shared__ float sW1[128 * 64];
    __shared__ float sW2[64 * 64];
    __shared__ float sW3[64 * 64];
    __shared__ float es[DEC_WARPS][128];
    __shared__ float hs[DEC_WARPS][64];
    const int lane = threadIdx.x & 31;
    const int w = threadIdx.x >> 5;
    for (int i = threadIdx.x; i < 128 * 64; i += blockDim.x) sW1[i] = Wm1[i];
    for (int i = threadIdx.x; i < 64 * 64; i += blockDim.x) { sW2[i] = Wm2[i]; sW3[i] = Wm3[i]; }
    __syncthreads();
    int gw = blockIdx.x * DEC_WARPS + w;
    int stride = gridDim.x * DEC_WARPS;
    const int c2 = 2 * lane;
    for (int t = gw; t < L_EDGES; t += stride) {
        int s = eli[t], d = eli[L_EDGES + t];
        *(float2*)&es[w][c2]      = *(const float2*)&g_z[(size_t)s * 64 + c2];
        *(float2*)&es[w][64 + c2] = *(const float2*)&g_z[(size_t)d * 64 + c2];
        __syncwarp();
        {
            float2 bb = *(const float2*)&bm1[c2];
            u64 a0 = pk2(bb.x, bb.y), a1 = 0ULL, a2 = 0ULL, a3 = 0ULL;
            #pragma unroll
            for (int k = 0; k < 128; k += 4) {
                float4 ev = *(const float4*)&es[w][k];
                float2 w0 = *(const float2*)&sW1[(k + 0) * 64 + c2];
                float2 w1 = *(const float2*)&sW1[(k + 1) * 64 + c2];
                float2 w2 = *(const float2*)&sW1[(k + 2) * 64 + c2];
                float2 w3 = *(const float2*)&sW1[(k + 3) * 64 + c2];
                fma2(a0, dup2(ev.x), pk2(w0.x, w0.y));
                fma2(a1, dup2(ev.y), pk2(w1.x, w1.y));
                fma2(a2, dup2(ev.z), pk2(w2.x, w2.y));
                fma2(a3, dup2(ev.w), pk2(w3.x, w3.y));
            }
            add2(a0, a1); add2(a2, a3); add2(a0, a2);
            float r0, r1; unpk2(r0, r1, a0);
            __syncwarp();
            hs[w][c2] = fmaxf(r0, 0.f); hs[w][c2 + 1] = fmaxf(r1, 0.f);
            __syncwarp();
        }
        #pragma unroll
        for (int L = 0; L < 2; L++) {
            const float* Wl = L == 0 ? sW2 : sW3;
            const float* bl = L == 0 ? bm2 : bm3;
            float2 bb = *(const float2*)&bl[c2];
            u64 a0 = pk2(bb.x, bb.y), a1 = 0ULL, a2 = 0ULL, a3 = 0ULL;
            #pragma unroll
            for (int k = 0; k < 64; k += 4) {
                float4 ev = *(const float4*)&hs[w][k];
                float2 w0 = *(const float2*)&Wl[(k + 0) * 64 + c2];
                float2 w1 = *(const float2*)&Wl[(k + 1) * 64 + c2];
                float2 w2 = *(const float2*)&Wl[(k + 2) * 64 + c2];
                float2 w3 = *(const float2*)&Wl[(k + 3) * 64 + c2];
                fma2(a0, dup2(ev.x), pk2(w0.x, w0.y));
                fma2(a1, dup2(ev.y), pk2(w1.x, w1.y));
                fma2(a2, dup2(ev.z), pk2(w2.x, w2.y));
                fma2(a3, dup2(ev.w), pk2(w3.x, w3.y));
            }
            add2(a0, a1); add2(a2, a3); add2(a0, a2);
            float r0, r1; unpk2(r0, r1, a0);
            __syncwarp();
            hs[w][c2] = fmaxf(r0, 0.f); hs[w][c2 + 1] = fmaxf(r1, 0.f);
            __syncwarp();
        }
        float2 hv = *(const float2*)&hs[w][c2];
        float o0 = hv.x * __ldg(&Wm4[c2 * 3 + 0]) + hv.y * __ldg(&Wm4[(c2 + 1) * 3 + 0]);
        float o1 = hv.x * __ldg(&Wm4[c2 * 3 + 1]) + hv.y * __ldg(&Wm4[(c2 + 1) * 3 + 1]);
        float o2 = hv.x * __ldg(&Wm4[c2 * 3 + 2]) + hv.y * __ldg(&Wm4[(c2 + 1) * 3 + 2]);
        #pragma unroll
        for (int off = 16; off; off >>= 1) {
            o0 += __shfl_down_sync(0xffffffffu, o0, off);
            o1 += __shfl_down_sync(0xffffffffu, o1, off);
            o2 += __shfl_down_sync(0xffffffffu, o2, off);
        }
        if (lane == 0) {
            o0 += __ldg(&bm4[0]); o1 += __ldg(&bm4[1]); o2 += __ldg(&bm4[2]);
            int   idx  = 0;
            float best = o0;
            if (o1 > best) { best = o1; idx = 1; }
            if (o2 > best) { best = o2; idx = 2; }
            out[t]           = (float)idx;
            out[L_EDGES + t] = best;
            out[2 * L_EDGES + t * 3 + 0] = o0;
            out[2 * L_EDGES + t * 3 + 1] = o1;
            out[2 * L_EDGES + t * 3 + 2] = o2;
        }
        __syncwarp();
    }
}

// ---------------- host launch ----------------
static inline int cdiv(int a, int b) { return (a + b - 1) / b; }

extern "C" void kernel_launch(void* const* d_in, const int* in_sizes, int n_in,
                              void* d_out, int out_size) {
    const float* x   = (const float*)d_in[0];
    const int*   ei  = (const int*)d_in[1];
    const int*   hn  = (const int*)d_in[2];
    const int*   he  = (const int*)d_in[3];
    const int*   eli = (const int*)d_in[4];
    const float* W1  = (const float*)d_in[5];
    const float* b1  = (const float*)d_in[6];
    const float* W2  = (const float*)d_in[7];
    const float* a2s = (const float*)d_in[8];
    const float* a2d = (const float*)d_in[9];
    const float* b2  = (const float*)d_in[10];
    const float* W3  = (const float*)d_in[11];
    const float* a3s = (const float*)d_in[12];
    const float* a3d = (const float*)d_in[13];
    const float* b3  = (const float*)d_in[14];
    const float* Wm1 = (const float*)d_in[15];
    const float* bm1 = (const float*)d_in[16];
    const float* Wm2 = (const float*)d_in[17];
    const float* bm2 = (const float*)d_in[18];
    const float* Wm3 = (const float*)d_in[19];
    const float* bm3 = (const float*)d_in[20];
    const float* Wm4 = (const float*)d_in[21];
    const float* bm4 = (const float*)d_in[22];
    float* out = (float*)d_out;

    void *p_cnt_he, *p_cnt_nd, *p_cnt_g, *p_h0, *p_h1, *p_hg, *p_z, *p_m;
    cudaGetSymbolAddress(&p_cnt_he, c_cnt_he);
    cudaGetSymbolAddress(&p_cnt_nd, c_cnt_nd);
    cudaGetSymbolAddress(&p_cnt_g,  c_cnt_g);
    cudaGetSymbolAddress(&p_h0, g_h0);
    cudaGetSymbolAddress(&p_h1, g_h1);
    cudaGetSymbolAddress(&p_hg, g_hg);
    cudaGetSymbolAddress(&p_z,  g_z);
    cudaGetSymbolAddress(&p_m,  g_m);

    const int TB = 256;
    float* t_stage = (float*)p_h0;   // logit staging buffer (g_h0 free after hconv GEMM)

    // ===== CSR builds =====
    cudaMemsetAsync(p_cnt_he, 0, sizeof(int) * N_HE, 0);
    cudaMemsetAsync(p_cnt_nd, 0, sizeof(int) * N_NODES, 0);
    cudaMemsetAsync(p_cnt_g,  0, sizeof(int) * N_NODES, 0);
    k_cnt_all<<<cdiv(N_PAIRS + E2, TB), TB>>>(hn, he, ei);
    k_scan3<<<3, 1024>>>();
    k_fill_all<<<cdiv(N_PAIRS + E2, TB), TB>>>(hn, he, ei);

    // ===== hypergraph conv: gather x (128d) -> GEMM on hyperedges -> node gather =====
    k_hc_edge_gather128<<<cdiv(N_HE * 32, TB), TB>>>(x);
    sgemm<128, 128, 16, 8, 8><<<dim3(2, cdiv(N_HE, 128)), 256>>>(
        (float*)p_h0, W1, (float*)p_m, N_HE, 256, 128);
    k_hc_node_gather<<<cdiv(N_NODES * 32, TB), TB>>>(b1);

    // ===== GAT layer 1 (256 -> 256) =====
    sgemm<128, 128, 16, 8, 8><<<dim3(2, cdiv(N_NODES, 128)), 256>>>(
        (float*)p_h1, W2, (float*)p_hg, N_NODES, 256, 256);
    k_dots<256><<<cdiv(N_NODES * 32, TB), TB>>>(a2s, a2d);
    k_gat_logits<<<cdiv(E2, TB), TB>>>(t_stage);
    k_gat_aggr<256><<<cdiv(N_NODES * 32, TB), TB>>>(t_stage, b2, (float*)p_h1);

    // ===== GAT layer 2 (256 -> 64) =====
    sgemm<128, 64, 16, 8, 4><<<dim3(1, cdiv(N_NODES, 128)), 256>>>(
        (float*)p_h1, W3, (float*)p_hg, N_NODES, 64, 256);
    k_dots<64><<<cdiv(N_NODES * 32, TB), TB>>>(a3s, a3d);
    k_gat_logits<<<cdiv(E2, TB), TB>>>(t_stage);
    k_gat_aggr<64><<<cdiv(N_NODES * 32, TB), TB>>>(t_stage, b3, (float*)p_z);

    // ===== decode MLP =====
    decode_kernel<<<740, TB>>>(eli, Wm1, bm1, Wm2, bm2, Wm3, bm3, Wm4, bm4, out);
}

// round 8
// speedup vs baseline: 1.2816x; 1.2281x over previous
#include <cuda_runtime.h>
#include <math.h>

#define N_NODES   50000
#define N_HE      20000
#define N_PAIRS   400000
#define E_EDGES   800000
#define E2        (E_EDGES + N_NODES)
#define L_EDGES   100000

// ---------------- scratch (device globals; no runtime allocation) ----------------
__device__ float g_h0[N_NODES * 256];   // hconv: m128 staging
__device__ float g_m [N_HE    * 256];   // hyperedge messages post-GEMM
__device__ float g_h1[N_NODES * 256];   // activations; decode: MLP ping-pong buffers
__device__ float g_hg[N_NODES * 256];   // GEMM output features; decode: edge features E
__device__ float g_as[N_NODES];
__device__ float g_ad[N_NODES];
__device__ float g_z [N_NODES * 64];

// CSR: single backing array for counts (one memset)
__device__ int c_cnt[N_HE + N_NODES + N_NODES];
#define c_cnt_he (c_cnt)
#define c_cnt_nd (c_cnt + N_HE)
#define c_cnt_g  (c_cnt + N_HE + N_NODES)
__device__ int c_off_he[N_HE],    c_cur_he[N_HE],    c_val_he[N_PAIRS];
__device__ int c_off_nd[N_NODES], c_cur_nd[N_NODES], c_val_nd[N_PAIRS];
__device__ int c_off_g [N_NODES], c_cur_g [N_NODES], c_val_g [E2];

typedef unsigned long long u64;

__device__ __forceinline__ float lrelu02(float x) { return x > 0.f ? x : 0.2f * x; }
__device__ __forceinline__ void f4add(float4& a, const float4 b) {
    a.x += b.x; a.y += b.y; a.z += b.z; a.w += b.w;
}
__device__ __forceinline__ void f4fma(float4& a, float w, const float4 b) {
    a.x = fmaf(w, b.x, a.x); a.y = fmaf(w, b.y, a.y);
    a.z = fmaf(w, b.z, a.z); a.w = fmaf(w, b.w, a.w);
}
// ---- packed fp32x2 (Blackwell FFMA2) ----
__device__ __forceinline__ u64 pk2(float lo, float hi) {
    u64 r; asm("mov.b64 %0, {%1, %2};" : "=l"(r) : "f"(lo), "f"(hi)); return r;
}
__device__ __forceinline__ u64 dup2(float x) { return pk2(x, x); }
__device__ __forceinline__ void unpk2(float& lo, float& hi, u64 v) {
    asm("mov.b64 {%0, %1}, %2;" : "=f"(lo), "=f"(hi) : "l"(v));
}
__device__ __forceinline__ void fma2(u64& d, u64 a, u64 b) {
    asm("fma.rn.f32x2 %0, %1, %2, %0;" : "+l"(d) : "l"(a), "l"(b));
}

// ---------------- GEMM: C[M,N] = A[M,K] @ B[K,N], fp32, f32x2 core, double-buffered.
// EPI: fused C = relu(C + bias[col]).
template<int BM, int BN, int BK, int TM, int TN, bool EPI>
__global__ void __launch_bounds__((BM / TM) * (BN / TN))
sgemm(const float* __restrict__ A, const float* __restrict__ B, float* __restrict__ C,
      int M, int N, int K, const float* __restrict__ bias) {
    constexpr int NT = (BM / TM) * (BN / TN);
    constexpr int LA = BM * BK / 4 / NT;
    constexpr int LB = BK * BN / 4 / NT;
    __shared__ float As[2][BK][BM + 4];
    __shared__ float Bs[2][BK][BN];
    const int tid = threadIdx.x;
    const int tx = tid % (BN / TN);
    const int ty = tid / (BN / TN);
    const int rowBase = blockIdx.y * BM, colBase = blockIdx.x * BN;
    float4 ra[LA], rb[LB];

    auto loadA = [&](int k0) {
        #pragma unroll
        for (int s = 0; s < LA; s++) {
            int f = tid + s * NT;
            int r = f / (BK / 4), c = (f % (BK / 4)) * 4;
            int gr = rowBase + r;
            ra[s] = (gr < M) ? *(const float4*)&A[(size_t)gr * K + k0 + c]
                             : make_float4(0.f, 0.f, 0.f, 0.f);
        }
    };
    auto loadB = [&](int k0) {
        #pragma unroll
        for (int s = 0; s < LB; s++) {
            int f = tid + s * NT;
            int r = f / (BN / 4), c = (f % (BN / 4)) * 4;
            rb[s] = *(const float4*)&B[(size_t)(k0 + r) * N + colBase + c];
        }
    };
    auto stA = [&](int buf) {
        #pragma unroll
        for (int s = 0; s < LA; s++) {
            int f = tid + s * NT;
            int r = f / (BK / 4), c = (f % (BK / 4)) * 4;
            As[buf][c + 0][r] = ra[s].x; As[buf][c + 1][r] = ra[s].y;
            As[buf][c + 2][r] = ra[s].z; As[buf][c + 3][r] = ra[s].w;
        }
    };
    auto stB = [&](int buf) {
        #pragma unroll
        for (int s = 0; s < LB; s++) {
            int f = tid + s * NT;
            int r = f / (BN / 4), c = (f % (BN / 4)) * 4;
            *(float4*)&Bs[buf][r][c] = rb[s];
        }
    };

    u64 acc[TM][TN / 2];
    #pragma unroll
    for (int i = 0; i < TM; i++)
        #pragma unroll
        for (int j = 0; j < TN / 2; j++) acc[i][j] = 0ULL;

    loadA(0); loadB(0); stA(0); stB(0);
    __syncthreads();
    const int T = K / BK;
    int cur = 0;
    for (int t = 0; t < T; t++) {
        if (t + 1 < T) { loadA((t + 1) * BK); loadB((t + 1) * BK); }
        #pragma unroll
        for (int k = 0; k < BK; k++) {
            float af[TM], bf[TN];
            #pragma unroll
            for (int i = 0; i < TM; i += 4)
                *(float4*)&af[i] = *(const float4*)&As[cur][k][ty * TM + i];
            #pragma unroll
            for (int j = 0; j < TN; j += 4)
                *(float4*)&bf[j] = *(const float4*)&Bs[cur][k][tx * TN + j];
            u64 a2[TM], b2[TN / 2];
            #pragma unroll
            for (int i = 0; i < TM; i++) a2[i] = dup2(af[i]);
            #pragma unroll
            for (int j = 0; j < TN / 2; j++) b2[j] = pk2(bf[2 * j], bf[2 * j + 1]);
            #pragma unroll
            for (int i = 0; i < TM; i++)
                #pragma unroll
                for (int j = 0; j < TN / 2; j++) fma2(acc[i][j], a2[i], b2[j]);
        }
        if (t + 1 < T) {
            stA(cur ^ 1); stB(cur ^ 1);
            __syncthreads();
            cur ^= 1;
        }
    }
    float bb[TN];
    if constexpr (EPI) {
        #pragma unroll
        for (int j = 0; j < TN; j++) bb[j] = __ldg(&bias[colBase + tx * TN + j]);
    }
    #pragma unroll
    for (int i = 0; i < TM; i++) {
        int gr = rowBase + ty * TM + i;
        if (gr < M) {
            #pragma unroll
            for (int j = 0; j < TN / 4; j++) {
                float4 v;
                unpk2(v.x, v.y, acc[i][2 * j]);
                unpk2(v.z, v.w, acc[i][2 * j + 1]);
                if constexpr (EPI) {
                    v.x = fmaxf(v.x + bb[4 * j + 0], 0.f);
                    v.y = fmaxf(v.y + bb[4 * j + 1], 0.f);
                    v.z = fmaxf(v.z + bb[4 * j + 2], 0.f);
                    v.w = fmaxf(v.w + bb[4 * j + 3], 0.f);
                }
                *(float4*)&C[(size_t)gr * N + colBase + tx * TN + 4 * j] = v;
            }
        }
    }
}

// ---------------- CSR build ----------------
__global__ void k_cnt_all(const int* __restrict__ hn, const int* __restrict__ he,
                          const int* __restrict__ ei) {
    int i = blockIdx.x * blockDim.x + threadIdx.x;
    if (i < N_PAIRS) {
        atomicAdd(&c_cnt_nd[hn[i]], 1);
        atomicAdd(&c_cnt_he[he[i]], 1);
    }
    int t = i - N_PAIRS;
    if (t >= 0 && t < E2) {
        int d = (t < E_EDGES) ? ei[E_EDGES + t] : (t - E_EDGES);
        atomicAdd(&c_cnt_g[d], 1);
    }
}

__device__ void scan_block(const int* __restrict__ in, int* __restrict__ off,
                           int* __restrict__ cur, int n) {
    const int tid = threadIdx.x;
    const int lane = tid & 31, wid = tid >> 5;
    __shared__ int wsums[32];
    __shared__ int s_tot;
    int carry = 0;
    for (int base = 0; base < n; base += 8192) {
        int i0 = base + tid * 8;
        int o[8], v[8];
        #pragma unroll
        for (int j = 0; j < 8; j++) o[j] = (i0 + j < n) ? in[i0 + j] : 0;
        v[0] = o[0];
        #pragma unroll
        for (int j = 1; j < 8; j++) v[j] = v[j - 1] + o[j];
        int tsum = v[7];
        int x = tsum;
        #pragma unroll
        for (int d = 1; d < 32; d <<= 1) {
            int y = __shfl_up_sync(0xffffffffu, x, d);
            if (lane >= d) x += y;
        }
        if (lane == 31) wsums[wid] = x;
        __syncthreads();
        if (wid == 0) {
            int y = wsums[lane], z = y;
            #pragma unroll
            for (int d = 1; d < 32; d <<= 1) {
                int u = __shfl_up_sync(0xffffffffu, z, d);
                if (lane >= d) z += u;
            }
            if (lane == 31) s_tot = z;
            wsums[lane] = z - y;
        }
        __syncthreads();
        int offv = carry + wsums[wid] + (x - tsum);
        #pragma unroll
        for (int j = 0; j < 8; j++) {
            if (i0 + j < n) {
                int e = offv + v[j] - o[j];
                off[i0 + j] = e;
                cur[i0 + j] = e;
            }
        }
        carry += s_tot;
        __syncthreads();
    }
}
__global__ void __launch_bounds__(1024) k_scan3() {
    if (blockIdx.x == 0)      scan_block(c_cnt_he, c_off_he, c_cur_he, N_HE);
    else if (blockIdx.x == 1) scan_block(c_cnt_nd, c_off_nd, c_cur_nd, N_NODES);
    else                      scan_block(c_cnt_g,  c_off_g,  c_cur_g,  N_NODES);
}

__global__ void k_fill_all(const int* __restrict__ hn, const int* __restrict__ he,
                           const int* __restrict__ ei) {
    int i = blockIdx.x * blockDim.x + threadIdx.x;
    if (i < N_PAIRS) {
        int n = hn[i], e = he[i];
        c_val_he[atomicAdd(&c_cur_he[e], 1)] = n;
        c_val_nd[atomicAdd(&c_cur_nd[n], 1)] = e;
    }
    int t = i - N_PAIRS;
    if (t >= 0 && t < E2) {
        int s, d;
        if (t < E_EDGES) { s = ei[t]; d = ei[E_EDGES + t]; } else { s = d = t - E_EDGES; }
        c_val_g[atomicAdd(&c_cur_g[d], 1)] = s;
    }
}

// ---------------- hypergraph conv ----------------
__global__ void k_hc_edge_gather128(const float* __restrict__ x) {
    int gw = (blockIdx.x * blockDim.x + threadIdx.x) >> 5;
    int lane = threadIdx.x & 31;
    if (gw >= N_HE) return;
    int deg = c_cnt_he[gw], start = c_off_he[gw];
    float4 a = {0, 0, 0, 0};
    int i = 0;
    for (; i + 4 <= deg; i += 4) {
        int n0 = c_val_he[start + i],     n1 = c_val_he[start + i + 1];
        int n2 = c_val_he[start + i + 2], n3 = c_val_he[start + i + 3];
        float4 x0 = ((const float4*)(x + (size_t)n0 * 128))[lane];
        float4 x1 = ((const float4*)(x + (size_t)n1 * 128))[lane];
        float4 x2 = ((const float4*)(x + (size_t)n2 * 128))[lane];
        float4 x3 = ((const float4*)(x + (size_t)n3 * 128))[lane];
        f4add(a, x0); f4add(a, x1); f4add(a, x2); f4add(a, x3);
    }
    for (; i < deg; i++) {
        f4add(a, ((const float4*)(x + (size_t)c_val_he[start + i] * 128))[lane]);
    }
    float binv = deg > 0 ? 1.f / (float)deg : 0.f;
    a.x *= binv; a.y *= binv; a.z *= binv; a.w *= binv;
    ((float4*)(g_h0 + (size_t)gw * 128))[lane] = a;
}
__global__ void k_hc_node_gather(const float* __restrict__ b1) {
    int gw = (blockIdx.x * blockDim.x + threadIdx.x) >> 5;
    int lane = threadIdx.x & 31;
    if (gw >= N_NODES) return;
    int deg = c_cnt_nd[gw], start = c_off_nd[gw];
    float4 a0 = {0, 0, 0, 0}, a1 = {0, 0, 0, 0};
    int i = 0;
    for (; i + 4 <= deg; i += 4) {
        const float4* p0 = (const float4*)(g_m + (size_t)c_val_nd[start + i] * 256);
        const float4* p1 = (const float4*)(g_m + (size_t)c_val_nd[start + i + 1] * 256);
        const float4* p2 = (const float4*)(g_m + (size_t)c_val_nd[start + i + 2] * 256);
        const float4* p3 = (const float4*)(g_m + (size_t)c_val_nd[start + i + 3] * 256);
        float4 x0a = p0[lane], x0b = p0[lane + 32];
        float4 x1a = p1[lane], x1b = p1[lane + 32];
        float4 x2a = p2[lane], x2b = p2[lane + 32];
        float4 x3a = p3[lane], x3b = p3[lane + 32];
        f4add(a0, x0a); f4add(a1, x0b);
        f4add(a0, x1a); f4add(a1, x1b);
        f4add(a0, x2a); f4add(a1, x2b);
        f4add(a0, x3a); f4add(a1, x3b);
    }
    for (; i < deg; i++) {
        const float4* p0 = (const float4*)(g_m + (size_t)c_val_nd[start + i] * 256);
        f4add(a0, p0[lane]); f4add(a1, p0[lane + 32]);
    }
    float dinv = deg > 0 ? 1.f / (float)deg : 0.f;
    float4 bb0 = __ldg((const float4*)b1 + lane);
    float4 bb1 = __ldg((const float4*)b1 + lane + 32);
    float4 r0, r1;
    r0.x = fmaxf(a0.x * dinv + bb0.x, 0.f); r0.y = fmaxf(a0.y * dinv + bb0.y, 0.f);
    r0.z = fmaxf(a0.z * dinv + bb0.z, 0.f); r0.w = fmaxf(a0.w * dinv + bb0.w, 0.f);
    r1.x = fmaxf(a1.x * dinv + bb1.x, 0.f); r1.y = fmaxf(a1.y * dinv + bb1.y, 0.f);
    r1.z = fmaxf(a1.z * dinv + bb1.z, 0.f); r1.w = fmaxf(a1.w * dinv + bb1.w, 0.f);
    float4* dst = (float4*)(g_h1 + (size_t)gw * 256);
    dst[lane] = r0;
    dst[lane + 32] = r1;
}

// ---------------- GAT ----------------
__global__ void k_dots256(const float* __restrict__ a_s, const float* __restrict__ a_d) {
    int gw = (blockIdx.x * blockDim.x + threadIdx.x) >> 5;
    int lane = threadIdx.x & 31;
    if (gw >= N_NODES) return;
    float s0 = 0.f, s1 = 0.f;
    const float4* h = (const float4*)(g_hg + (size_t)gw * 256);
    #pragma unroll
    for (int j = lane; j < 64; j += 32) {
        float4 v = h[j];
        float4 as4 = __ldg((const float4*)a_s + j);
        float4 ad4 = __ldg((const float4*)a_d + j);
        s0 += v.x * as4.x + v.y * as4.y + v.z * as4.z + v.w * as4.w;
        s1 += v.x * ad4.x + v.y * ad4.y + v.z * ad4.z + v.w * ad4.w;
    }
    #pragma unroll
    for (int off = 16; off; off >>= 1) {
        s0 += __shfl_down_sync(0xffffffffu, s0, off);
        s1 += __shfl_down_sync(0xffffffffu, s1, off);
    }
    if (lane == 0) { g_as[gw] = s0; g_ad[gw] = s1; }
}
// C=64: two nodes per warp (16 lanes each)
__global__ void k_dots64(const float* __restrict__ a_s, const float* __restrict__ a_d) {
    int warp = (blockIdx.x * blockDim.x + threadIdx.x) >> 5;
    int lane = threadIdx.x & 31;
    int node = warp * 2 + (lane >> 4);
    if (node >= N_NODES) return;
    int j = lane & 15;
    float4 v = ((const float4*)(g_hg + (size_t)node * 64))[j];
    float4 as4 = __ldg((const float4*)a_s + j);
    float4 ad4 = __ldg((const float4*)a_d + j);
    float s0 = v.x * as4.x + v.y * as4.y + v.z * as4.z + v.w * as4.w;
    float s1 = v.x * ad4.x + v.y * ad4.y + v.z * ad4.z + v.w * ad4.w;
    #pragma unroll
    for (int off = 8; off; off >>= 1) {
        s0 += __shfl_xor_sync(0xffffffffu, s0, off);
        s1 += __shfl_xor_sync(0xffffffffu, s1, off);
    }
    if (j == 0) { g_as[node] = s0; g_ad[node] = s1; }
}

// warp per dst node: softmax over incoming edges + weighted gather + bias + relu
template <int C>
__global__ void k_gat_aggr(const float* __restrict__ bias, float* __restrict__ dst) {
    int gw = (blockIdx.x * blockDim.x + threadIdx.x) >> 5;
    int lane = threadIdx.x & 31;
    if (gw >= N_NODES) return;
    int deg = c_cnt_g[gw], start = c_off_g[gw];
    float adst = g_ad[gw];
    float mx = -1e30f;
    for (int i = lane; i < deg; i += 32)
        mx = fmaxf(mx, lrelu02(g_as[c_val_g[start + i]] + adst));
    #pragma unroll
    for (int off = 16; off; off >>= 1)
        mx = fmaxf(mx, __shfl_xor_sync(0xffffffffu, mx, off));
    float sm = 0.f;
    for (int i = lane; i < deg; i += 32)
        sm += expf(lrelu02(g_as[c_val_g[start + i]] + adst) - mx);
    #pragma unroll
    for (int off = 16; off; off >>= 1)
        sm += __shfl_xor_sync(0xffffffffu, sm, off);
    float inv = 1.f / (sm + 1e-16f);
    if constexpr (C == 256) {
        float4 a0 = {0, 0, 0, 0}, a1 = {0, 0, 0, 0};
        int i = 0;
        for (; i + 4 <= deg; i += 4) {
            int s0 = c_val_g[start + i],     s1 = c_val_g[start + i + 1];
            int s2 = c_val_g[start + i + 2], s3 = c_val_g[start + i + 3];
            float w0 = expf(lrelu02(g_as[s0] + adst) - mx) * inv;
            float w1 = expf(lrelu02(g_as[s1] + adst) - mx) * inv;
            float w2 = expf(lrelu02(g_as[s2] + adst) - mx) * inv;
            float w3 = expf(lrelu02(g_as[s3] + adst) - mx) * inv;
            const float4* p0 = (const float4*)(g_hg + (size_t)s0 * 256);
            const float4* p1 = (const float4*)(g_hg + (size_t)s1 * 256);
            const float4* p2 = (const float4*)(g_hg + (size_t)s2 * 256);
            const float4* p3 = (const float4*)(g_hg + (size_t)s3 * 256);
            float4 x0a = p0[lane], x0b = p0[lane + 32];
            float4 x1a = p1[lane], x1b = p1[lane + 32];
            float4 x2a = p2[lane], x2b = p2[lane + 32];
            float4 x3a = p3[lane], x3b = p3[lane + 32];
            f4fma(a0, w0, x0a); f4fma(a1, w0, x0b);
            f4fma(a0, w1, x1a); f4fma(a1, w1, x1b);
            f4fma(a0, w2, x2a); f4fma(a1, w2, x2b);
            f4fma(a0, w3, x3a); f4fma(a1, w3, x3b);
        }
        for (; i < deg; i++) {
            int s0 = c_val_g[start + i];
            float w0 = expf(lrelu02(g_as[s0] + adst) - mx) * inv;
            const float4* p0 = (const float4*)(g_hg + (size_t)s0 * 256);
            f4fma(a0, w0, p0[lane]); f4fma(a1, w0, p0[lane + 32]);
        }
        float4 bb0 = __ldg((const float4*)bias + lane);
        float4 bb1 = __ldg((const float4*)bias + lane + 32);
        float4 r0, r1;
        r0.x = fmaxf(a0.x + bb0.x, 0.f); r0.y = fmaxf(a0.y + bb0.y, 0.f);
        r0.z = fmaxf(a0.z + bb0.z, 0.f); r0.w = fmaxf(a0.w + bb0.w, 0.f);
        r1.x = fmaxf(a1.x + bb1.x, 0.f); r1.y = fmaxf(a1.y + bb1.y, 0.f);
        r1.z = fmaxf(a1.z + bb1.z, 0.f); r1.w = fmaxf(a1.w + bb1.w, 0.f);
        float4* o = (float4*)(dst + (size_t)gw * 256);
        o[lane] = r0;
        o[lane + 32] = r1;
    } else {
        float2 acc = {0, 0};
        int i = 0;
        for (; i + 4 <= deg; i += 4) {
            int s0 = c_val_g[start + i],     s1 = c_val_g[start + i + 1];
            int s2 = c_val_g[start + i + 2], s3 = c_val_g[start + i + 3];
            float w0 = expf(lrelu02(g_as[s0] + adst) - mx) * inv;
            float w1 = expf(lrelu02(g_as[s1] + adst) - mx) * inv;
            float w2 = expf(lrelu02(g_as[s2] + adst) - mx) * inv;
            float w3 = expf(lrelu02(g_as[s3] + adst) - mx) * inv;
            float2 x0 = *(const float2*)(g_hg + (size_t)s0 * 64 + 2 * lane);
            float2 x1 = *(const float2*)(g_hg + (size_t)s1 * 64 + 2 * lane);
            float2 x2 = *(const float2*)(g_hg + (size_t)s2 * 64 + 2 * lane);
            float2 x3 = *(const float2*)(g_hg + (size_t)s3 * 64 + 2 * lane);
            acc.x = fmaf(w0, x0.x, acc.x); acc.y = fmaf(w0, x0.y, acc.y);
            acc.x = fmaf(w1, x1.x, acc.x); acc.y = fmaf(w1, x1.y, acc.y);
            acc.x = fmaf(w2, x2.x, acc.x); acc.y = fmaf(w2, x2.y, acc.y);
            acc.x = fmaf(w3, x3.x, acc.x); acc.y = fmaf(w3, x3.y, acc.y);
        }
        for (; i < deg; i++) {
            int s0 = c_val_g[start + i];
            float w0 = expf(lrelu02(g_as[s0] + adst) - mx) * inv;
            float2 x0 = *(const float2*)(g_hg + (size_t)s0 * 64 + 2 * lane);
            acc.x = fmaf(w0, x0.x, acc.x); acc.y = fmaf(w0, x0.y, acc.y);
        }
        float2 bb = *(const float2*)(bias + 2 * lane);
        float2 r;
        r.x = fmaxf(acc.x + bb.x, 0.f);
        r.y = fmaxf(acc.y + bb.y, 0.f);
        *(float2*)(dst + (size_t)gw * 64 + 2 * lane) = r;
    }
}

// ---------------- decode: edge feature gather (warp per edge) ----------------
__global__ void k_egather(const int* __restrict__ eli, float* __restrict__ E) {
    int gw = (blockIdx.x * blockDim.x + threadIdx.x) >> 5;
    int lane = threadIdx.x & 31;
    if (gw >= L_EDGES) return;
    int s = eli[gw], d = eli[L_EDGES + gw];
    float2 a = *(const float2*)(g_z + (size_t)s * 64 + 2 * lane);
    float2 b = *(const float2*)(g_z + (size_t)d * 64 + 2 * lane);
    *(float2*)(E + (size_t)gw * 128 + 2 * lane)      = a;
    *(float2*)(E + (size_t)gw * 128 + 64 + 2 * lane) = b;
}

// ---------------- decode: final 64->3 + argmax (thread per edge) ----------------
__global__ void k_final(const float* __restrict__ h,
                        const float* __restrict__ Wm4, const float* __restrict__ bm4,
                        float* __restrict__ out) {
    __shared__ float sW[64 * 3];
    __shared__ float sb[3];
    for (int i = threadIdx.x; i < 192; i += blockDim.x) sW[i] = Wm4[i];
    if (threadIdx.x < 3) sb[threadIdx.x] = bm4[threadIdx.x];
    __syncthreads();
    int t = blockIdx.x * blockDim.x + threadIdx.x;
    if (t >= L_EDGES) return;
    const float4* hp = (const float4*)(h + (size_t)t * 64);
    float o0 = sb[0], o1 = sb[1], o2 = sb[2];
    #pragma unroll
    for (int k4 = 0; k4 < 16; k4++) {
        float4 v = hp[k4];
        int k = k4 * 4;
        o0 = fmaf(v.x, sW[(k + 0) * 3 + 0], o0); o1 = fmaf(v.x, sW[(k + 0) * 3 + 1], o1); o2 = fmaf(v.x, sW[(k + 0) * 3 + 2], o2);
        o0 = fmaf(v.y, sW[(k + 1) * 3 + 0], o0); o1 = fmaf(v.y, sW[(k + 1) * 3 + 1], o1); o2 = fmaf(v.y, sW[(k + 1) * 3 + 2], o2);
        o0 = fmaf(v.z, sW[(k + 2) * 3 + 0], o0); o1 = fmaf(v.z, sW[(k + 2) * 3 + 1], o1); o2 = fmaf(v.z, sW[(k + 2) * 3 + 2], o2);
        o0 = fmaf(v.w, sW[(k + 3) * 3 + 0], o0); o1 = fmaf(v.w, sW[(k + 3) * 3 + 1], o1); o2 = fmaf(v.w, sW[(k + 3) * 3 + 2], o2);
    }
    int   idx  = 0;
    float best = o0;
    if (o1 > best) { best = o1; idx = 1; }
    if (o2 > best) { best = o2; idx = 2; }
    out[t]           = (float)idx;
    out[L_EDGES + t] = best;
    out[2 * L_EDGES + t * 3 + 0] = o0;
    out[2 * L_EDGES + t * 3 + 1] = o1;
    out[2 * L_EDGES + t * 3 + 2] = o2;
}

// ---------------- host launch ----------------
static inline int cdiv(int a, int b) { return (a + b - 1) / b; }

extern "C" void kernel_launch(void* const* d_in, const int* in_sizes, int n_in,
                              void* d_out, int out_size) {
    const float* x   = (const float*)d_in[0];
    const int*   ei  = (const int*)d_in[1];
    const int*   hn  = (const int*)d_in[2];
    const int*   he  = (const int*)d_in[3];
    const int*   eli = (const int*)d_in[4];
    const float* W1  = (const float*)d_in[5];
    const float* b1  = (const float*)d_in[6];
    const float* W2  = (const float*)d_in[7];
    const float* a2s = (const float*)d_in[8];
    const float* a2d = (const float*)d_in[9];
    const float* b2  = (const float*)d_in[10];
    const float* W3  = (const float*)d_in[11];
    const float* a3s = (const float*)d_in[12];
    const float* a3d = (const float*)d_in[13];
    const float* b3  = (const float*)d_in[14];
    const float* Wm1 = (const float*)d_in[15];
    const float* bm1 = (const float*)d_in[16];
    const float* Wm2 = (const float*)d_in[17];
    const float* bm2 = (const float*)d_in[18];
    const float* Wm3 = (const float*)d_in[19];
    const float* bm3 = (const float*)d_in[20];
    const float* Wm4 = (const float*)d_in[21];
    const float* bm4 = (const float*)d_in[22];
    float* out = (float*)d_out;

    void *p_cnt, *p_h0, *p_h1, *p_hg, *p_z, *p_m;
    cudaGetSymbolAddress(&p_cnt, c_cnt);
    cudaGetSymbolAddress(&p_h0, g_h0);
    cudaGetSymbolAddress(&p_h1, g_h1);
    cudaGetSymbolAddress(&p_hg, g_hg);
    cudaGetSymbolAddress(&p_z,  g_z);
    cudaGetSymbolAddress(&p_m,  g_m);

    const int TB = 256;

    // ===== CSR builds (single memset) =====
    cudaMemsetAsync(p_cnt, 0, sizeof(int) * (N_HE + 2 * N_NODES), 0);
    k_cnt_all<<<cdiv(N_PAIRS + E2, TB), TB>>>(hn, he, ei);
    k_scan3<<<3, 1024>>>();
    k_fill_all<<<cdiv(N_PAIRS + E2, TB), TB>>>(hn, he, ei);

    // ===== hypergraph conv: gather x (128d) -> GEMM on hyperedges -> node gather =====
    k_hc_edge_gather128<<<cdiv(N_HE * 32, TB), TB>>>(x);
    sgemm<128, 128, 16, 8, 8, false><<<dim3(2, cdiv(N_HE, 128)), 256>>>(
        (float*)p_h0, W1, (float*)p_m, N_HE, 256, 128, nullptr);
    k_hc_node_gather<<<cdiv(N_NODES * 32, TB), TB>>>(b1);

    // ===== GAT layer 1 (256 -> 256) =====
    sgemm<128, 128, 16, 8, 8, false><<<dim3(2, cdiv(N_NODES, 128)), 256>>>(
        (float*)p_h1, W2, (float*)p_hg, N_NODES, 256, 256, nullptr);
    k_dots256<<<cdiv(N_NODES * 32, TB), TB>>>(a2s, a2d);
    k_gat_aggr<256><<<cdiv(N_NODES * 32, TB), TB>>>(b2, (float*)p_h1);

    // ===== GAT layer 2 (256 -> 64) =====
    sgemm<128, 64, 16, 8, 4, false><<<dim3(1, cdiv(N_NODES, 128)), 256>>>(
        (float*)p_h1, W3, (float*)p_hg, N_NODES, 64, 256, nullptr);
    k_dots64<<<cdiv(N_NODES * 16, TB), TB>>>(a3s, a3d);
    k_gat_aggr<64><<<cdiv(N_NODES * 32, TB), TB>>>(b3, (float*)p_z);

    // ===== decode MLP as GEMMs =====
    float* Ebuf = (float*)p_hg;                       // 100k x 128 edge features
    float* hA   = (float*)p_h1;                       // 100k x 64
    float* hB   = (float*)p_h1 + (size_t)L_EDGES * 64;
    k_egather<<<cdiv(L_EDGES * 32, TB), TB>>>(eli, Ebuf);
    sgemm<128, 64, 16, 8, 4, true><<<dim3(1, cdiv(L_EDGES, 128)), 256>>>(
        Ebuf, Wm1, hA, L_EDGES, 64, 128, bm1);
    sgemm<128, 64, 16, 8, 4, true><<<dim3(1, cdiv(L_EDGES, 128)), 256>>>(
        hA, Wm2, hB, L_EDGES, 64, 64, bm2);
    sgemm<128, 64, 16, 8, 4, true><<<dim3(1, cdiv(L_EDGES, 128)), 256>>>(
        hB, Wm3, hA, L_EDGES, 64, 64, bm3);
    k_final<<<cdiv(L_EDGES, TB), TB>>>(hA, Wm4, bm4, out);
}